// round 5
// baseline (speedup 1.0000x reference)
#include <cuda_runtime.h>
#include <cstdint>

// ─────────────────────────────────────────────────────────────────────────────
// SecondOrderFeatureInteraction via mma.sync.m16n8k8.tf32 batched Gram.
//   out[b, pair(i,j)] = dot(x[b,i,:], x[b,j,:]), i<j.  B=8192, N=32, D=256.
// One warp owns one batch end-to-end: warp-private 3-stage cp.async pipeline
// (loads issued ahead of the wait, L2::256B prefetch hint), coalesced 4-line
// loads, 32x32 gram in 24 accumulators. Gram symmetry: B-fragments ==
// A-fragments, so 8 LDS + 6 MMA per k-step.
// ─────────────────────────────────────────────────────────────────────────────

static constexpr int NF = 32, DD = 256, NPAIRS = 496;
static constexpr int BLOCK = 256;                 // 8 warps
static constexpr int BPC = 8;                     // batches per CTA (1/warp)
static constexpr int KC = 32;                     // k-extent per stage
static constexpr int STAGE_BYTES = BPC * NF * KC * 4;   // 32 KB
static constexpr int NSTAGES = 3;
static constexpr int NKST = DD / KC;              // 8 k-stages

#define DI __device__ __forceinline__

DI uint32_t smem_u32(const void* p) {
    uint32_t a;
    asm("{ .reg .u64 t; cvta.to.shared.u64 t, %1; cvt.u32.u64 %0, t; }"
        : "=r"(a) : "l"(p));
    return a;
}

DI void cp_async16(uint32_t dst, const void* src) {
    asm volatile("cp.async.cg.shared.global.L2::256B [%0], [%1], 16;"
                 :: "r"(dst), "l"(src) : "memory");
}

DI float lds_f32(uint32_t a) {
    float v;
    asm volatile("ld.shared.f32 %0, [%1];" : "=f"(v) : "r"(a));
    return v;
}

DI uint32_t to_tf32(float f) {
    uint32_t r;
    asm("cvt.rna.tf32.f32 %0, %1;" : "=r"(r) : "f"(f));
    return r;
}

DI void mma_tf32(float* d, const uint32_t* a, uint32_t b0, uint32_t b1) {
    asm volatile(
        "mma.sync.aligned.m16n8k8.row.col.f32.tf32.tf32.f32 "
        "{%0,%1,%2,%3}, {%4,%5,%6,%7}, {%8,%9}, {%0,%1,%2,%3};"
        : "+f"(d[0]), "+f"(d[1]), "+f"(d[2]), "+f"(d[3])
        : "r"(a[0]), "r"(a[1]), "r"(a[2]), "r"(a[3]), "r"(b0), "r"(b1));
}

extern __shared__ char dynsmem[];

__global__ void __launch_bounds__(BLOCK, 2)
soi_mma_kernel(const float* __restrict__ x, float* __restrict__ out) {
    const uint32_t sb = smem_u32(dynsmem);
    const int tid = threadIdx.x, lane = tid & 31, wid = tid >> 5;
    const long long batch0 = (long long)blockIdx.x * BPC;
    // warp w's global base: its own batch's 32 rows
    const float* xg = x + (batch0 + wid) * (NF * DD);

    // ── warp-private stage loader: 32 rows x 32 floats (4 KB), coalesced.
    //    lane -> (rr = lane>>3 row-in-quad, cc = lane&7 16B chunk);
    //    instr i covers rows 4i..4i+3: 4 contiguous 128B lines per instr.
    const int rr = lane >> 3, cc = lane & 7;
    auto load_stage = [&](int ks) {
        const uint32_t buf = sb + (ks % NSTAGES) * STAGE_BYTES;
        #pragma unroll
        for (int i = 0; i < 8; i++) {
            const int row = 4 * i + rr;                       // row within batch
            const float* src = xg + (long long)row * DD + ks * KC + cc * 4;
            const uint32_t dst = buf + (uint32_t)(wid * NF + row) * 128
                               + (uint32_t)((cc ^ (row & 7)) << 4);
            cp_async16(dst, src);
        }
        asm volatile("cp.async.commit_group;" ::: "memory");
    };

    // ── fragment addressing (consumer layout identical to loader's dst) ──
    const int r7 = lane >> 2;                     // row-in-8, also swizzle key
    const uint32_t rowA = (uint32_t)(wid * NF + r7) * 128 + (lane & 3) * 4;

    float acc[6][4];
    #pragma unroll
    for (int t = 0; t < 6; t++)
        #pragma unroll
        for (int e = 0; e < 4; e++) acc[t][e] = 0.f;

    load_stage(0);
    load_stage(1);

    for (int ks = 0; ks < NKST; ks++) {
        // prefetch FIRST, then wait — keeps 3 groups in flight across the wait
        if (ks + 2 < NKST) {
            load_stage(ks + 2);
            asm volatile("cp.async.wait_group 2;" ::: "memory");
        } else if (ks + 1 < NKST) {
            asm volatile("cp.async.wait_group 1;" ::: "memory");
        } else {
            asm volatile("cp.async.wait_group 0;" ::: "memory");
        }
        __syncwarp();                              // warp-private buffers only

        const uint32_t buf = sb + (ks % NSTAGES) * STAGE_BYTES;
        #pragma unroll
        for (int kq = 0; kq < 4; kq++) {
            const uint32_t o0 = (uint32_t)(((2 * kq + 0) ^ r7) << 4);
            const uint32_t o1 = (uint32_t)(((2 * kq + 1) ^ r7) << 4);
            const uint32_t base = buf + rowA;
            uint32_t a[8];
            a[0] = to_tf32(lds_f32(base + o0));          // rows 0-7,  k lo
            a[1] = to_tf32(lds_f32(base + 1024 + o0));   // rows 8-15, k lo
            a[2] = to_tf32(lds_f32(base + o1));          // rows 0-7,  k hi
            a[3] = to_tf32(lds_f32(base + 1024 + o1));   // rows 8-15, k hi
            a[4] = to_tf32(lds_f32(base + 2048 + o0));   // rows 16-23, k lo
            a[5] = to_tf32(lds_f32(base + 3072 + o0));   // rows 24-31, k lo
            a[6] = to_tf32(lds_f32(base + 2048 + o1));   // rows 16-23, k hi
            a[7] = to_tf32(lds_f32(base + 3072 + o1));   // rows 24-31, k hi
            // Gram: b-fragments are the a-fragment registers (row.col, B=A^T)
            mma_tf32(acc[0], a + 0, a[0], a[2]);   // (m0, n0)
            mma_tf32(acc[1], a + 0, a[1], a[3]);   // (m0, n1)
            mma_tf32(acc[2], a + 0, a[4], a[6]);   // (m0, n2)
            mma_tf32(acc[3], a + 0, a[5], a[7]);   // (m0, n3)
            mma_tf32(acc[4], a + 4, a[4], a[6]);   // (m1, n2)
            mma_tf32(acc[5], a + 4, a[5], a[7]);   // (m1, n3)
        }
        __syncwarp();                              // reads done before refill next iter
    }

    // ── epilogue: scatter the strict upper triangle ──
    static const int IOFF[6] = { 0, 0, 0, 0, 16, 16 };
    static const int JOFF[6] = { 0, 8, 16, 24, 16, 24 };
    float* ob = out + (batch0 + wid) * NPAIRS;
    const int ib = lane >> 2, jb = 2 * (lane & 3);
    #pragma unroll
    for (int t = 0; t < 6; t++) {
        #pragma unroll
        for (int e = 0; e < 4; e++) {
            const int i = IOFF[t] + ib + 8 * (e >> 1);
            const int j = JOFF[t] + jb + (e & 1);
            if (j > i)
                ob[i * 31 - (i * (i - 1)) / 2 + (j - i - 1)] = acc[t][e];
        }
    }
}

extern "C" void kernel_launch(void* const* d_in, const int* in_sizes, int n_in,
                              void* d_out, int out_size) {
    const float* x = (const float*)d_in[0];
    float* out = (float*)d_out;
    const int nb = in_sizes[0] / (NF * DD);        // 8192
    cudaFuncSetAttribute(soi_mma_kernel,
                         cudaFuncAttributeMaxDynamicSharedMemorySize,
                         NSTAGES * STAGE_BYTES);
    soi_mma_kernel<<<nb / BPC, BLOCK, NSTAGES * STAGE_BYTES>>>(x, out);
}

// round 6
// speedup vs baseline: 1.0294x; 1.0294x over previous
#include <cuda_runtime.h>
#include <cstdint>

// ─────────────────────────────────────────────────────────────────────────────
// SecondOrderFeatureInteraction via mma.sync.m16n8k8.tf32 batched Gram.
//   out[b, pair(i,j)] = dot(x[b,i,:], x[b,j,:]), i<j.  B=8192, N=32, D=256.
// One warp owns one batch. KC=64 staging: 256B contiguous per row per stage
// (better HBM row-buffer locality), warp-private 2-stage cp.async pipeline,
// 32x32 gram in 24 accumulators. Gram symmetry: B-fragments == A-fragments.
// ─────────────────────────────────────────────────────────────────────────────

static constexpr int NF = 32, DD = 256, NPAIRS = 496;
static constexpr int BPC = 4;                     // batches per CTA (1/warp)
static constexpr int BLOCK = BPC * 32;            // 128 threads, 4 warps
static constexpr int KC = 64;                     // k-extent per stage
static constexpr int ROWB = KC * 4;               // 256 B per row per stage
static constexpr int STAGE_BYTES = BPC * NF * ROWB;      // 32 KB
static constexpr int NSTAGES = 2;
static constexpr int NKST = DD / KC;              // 4 k-stages

#define DI __device__ __forceinline__

DI uint32_t smem_u32(const void* p) {
    uint32_t a;
    asm("{ .reg .u64 t; cvta.to.shared.u64 t, %1; cvt.u32.u64 %0, t; }"
        : "=r"(a) : "l"(p));
    return a;
}

DI void cp_async16(uint32_t dst, const void* src) {
    asm volatile("cp.async.cg.shared.global [%0], [%1], 16;"
                 :: "r"(dst), "l"(src) : "memory");
}

DI float lds_f32(uint32_t a) {
    float v;
    asm volatile("ld.shared.f32 %0, [%1];" : "=f"(v) : "r"(a));
    return v;
}

DI uint32_t to_tf32(float f) {
    uint32_t r;
    asm("cvt.rna.tf32.f32 %0, %1;" : "=r"(r) : "f"(f));
    return r;
}

DI void mma_tf32(float* d, const uint32_t* a, uint32_t b0, uint32_t b1) {
    asm volatile(
        "mma.sync.aligned.m16n8k8.row.col.f32.tf32.tf32.f32 "
        "{%0,%1,%2,%3}, {%4,%5,%6,%7}, {%8,%9}, {%0,%1,%2,%3};"
        : "+f"(d[0]), "+f"(d[1]), "+f"(d[2]), "+f"(d[3])
        : "r"(a[0]), "r"(a[1]), "r"(a[2]), "r"(a[3]), "r"(b0), "r"(b1));
}

extern __shared__ char dynsmem[];

__global__ void __launch_bounds__(BLOCK, 3)
soi_mma_kernel(const float* __restrict__ x, float* __restrict__ out) {
    const uint32_t sb = smem_u32(dynsmem);
    const int tid = threadIdx.x, lane = tid & 31, wid = tid >> 5;
    const long long batch0 = (long long)blockIdx.x * BPC;
    const float* xg = x + (batch0 + wid) * (NF * DD);   // warp's own batch

    // ── warp-private stage loader: 32 rows x 64 floats (8 KB).
    //    lane -> (rr = lane>>4 in {0,1}: row-in-pair, cc = lane&15: 16B chunk);
    //    each instr reads 2 rows x 256B contiguous (2 lines per row).
    //    smem: row stride 256B, chunk swizzled by XOR(row&7) on low-3 bits.
    const int rr = lane >> 4, cc = lane & 15;
    auto load_stage = [&](int ks) {
        const uint32_t buf = sb + (ks & 1) * STAGE_BYTES;
        #pragma unroll
        for (int i = 0; i < 16; i++) {
            const int row = 2 * i + rr;
            const float* src = xg + (long long)row * DD + ks * KC + cc * 4;
            const uint32_t dst = buf + (uint32_t)(wid * NF + row) * ROWB
                               + (uint32_t)((cc ^ (row & 7)) << 4);
            cp_async16(dst, src);
        }
        asm volatile("cp.async.commit_group;" ::: "memory");
    };

    // ── fragment addressing ──
    const int r7 = lane >> 2;                     // row-in-8, swizzle key
    const uint32_t rowA = (uint32_t)(wid * NF + r7) * ROWB + (lane & 3) * 4;

    float acc[6][4];
    #pragma unroll
    for (int t = 0; t < 6; t++)
        #pragma unroll
        for (int e = 0; e < 4; e++) acc[t][e] = 0.f;

    load_stage(0);

    for (int ks = 0; ks < NKST; ks++) {
        if (ks + 1 < NKST) {
            load_stage(ks + 1);
            asm volatile("cp.async.wait_group 1;" ::: "memory");
        } else {
            asm volatile("cp.async.wait_group 0;" ::: "memory");
        }
        __syncwarp();                              // warp-private buffers only

        const uint32_t base = sb + (ks & 1) * STAGE_BYTES + rowA;
        #pragma unroll
        for (int kq = 0; kq < KC / 8; kq++) {      // 8 k-quads per stage
            const uint32_t o0 = (uint32_t)(((2 * kq + 0) ^ r7) << 4);
            const uint32_t o1 = (uint32_t)(((2 * kq + 1) ^ r7) << 4);
            uint32_t a[8];
            a[0] = to_tf32(lds_f32(base + o0));          // rows 0-7,  k lo
            a[1] = to_tf32(lds_f32(base + 2048 + o0));   // rows 8-15, k lo
            a[2] = to_tf32(lds_f32(base + o1));          // rows 0-7,  k hi
            a[3] = to_tf32(lds_f32(base + 2048 + o1));   // rows 8-15, k hi
            a[4] = to_tf32(lds_f32(base + 4096 + o0));   // rows 16-23, k lo
            a[5] = to_tf32(lds_f32(base + 6144 + o0));   // rows 24-31, k lo
            a[6] = to_tf32(lds_f32(base + 4096 + o1));   // rows 16-23, k hi
            a[7] = to_tf32(lds_f32(base + 6144 + o1));   // rows 24-31, k hi
            // Gram: b-fragments are the a-fragment registers (row.col, B=A^T)
            mma_tf32(acc[0], a + 0, a[0], a[2]);   // (m0, n0)
            mma_tf32(acc[1], a + 0, a[1], a[3]);   // (m0, n1)
            mma_tf32(acc[2], a + 0, a[4], a[6]);   // (m0, n2)
            mma_tf32(acc[3], a + 0, a[5], a[7]);   // (m0, n3)
            mma_tf32(acc[4], a + 4, a[4], a[6]);   // (m1, n2)
            mma_tf32(acc[5], a + 4, a[5], a[7]);   // (m1, n3)
        }
        __syncwarp();                              // reads done before refill
    }

    // ── epilogue: scatter the strict upper triangle ──
    static const int IOFF[6] = { 0, 0, 0, 0, 16, 16 };
    static const int JOFF[6] = { 0, 8, 16, 24, 16, 24 };
    float* ob = out + (batch0 + wid) * NPAIRS;
    const int ib = lane >> 2, jb = 2 * (lane & 3);
    #pragma unroll
    for (int t = 0; t < 6; t++) {
        #pragma unroll
        for (int e = 0; e < 4; e++) {
            const int i = IOFF[t] + ib + 8 * (e >> 1);
            const int j = JOFF[t] + jb + (e & 1);
            if (j > i)
                ob[i * 31 - (i * (i - 1)) / 2 + (j - i - 1)] = acc[t][e];
        }
    }
}

extern "C" void kernel_launch(void* const* d_in, const int* in_sizes, int n_in,
                              void* d_out, int out_size) {
    const float* x = (const float*)d_in[0];
    float* out = (float*)d_out;
    const int nb = in_sizes[0] / (NF * DD);        // 8192
    cudaFuncSetAttribute(soi_mma_kernel,
                         cudaFuncAttributeMaxDynamicSharedMemorySize,
                         NSTAGES * STAGE_BYTES);
    soi_mma_kernel<<<nb / BPC, BLOCK, NSTAGES * STAGE_BYTES>>>(x, out);
}